// round 15
// baseline (speedup 1.0000x reference)
#include <cuda_runtime.h>
#include <cuda_bf16.h>
#include <cstdint>
#include <math.h>

#define BATCH 8
#define CIN   96
#define COUT  192
#define NTOK  3136
#define NPOS  (BATCH * NTOK)
#define NPAD  3200

__device__ float d_y[BATCH * COUT * NTOK];
__device__ float d_stats[2 * COUT];
__device__ float d_m[BATCH * NTOK];
__device__ __nv_bfloat16 d_kThi[BATCH * NPAD * CIN];   // x as [b][tok][c]
__device__ __nv_bfloat16 d_kTlo[BATCH * NPAD * CIN];
__device__ __nv_bfloat16 d_xjThi[BATCH * NPAD * CIN];  // xj as [b][tok][c]
__device__ __nv_bfloat16 d_xjTlo[BATCH * NPAD * CIN];
__device__ __nv_bfloat16 d_whi[COUT * COUT];
__device__ __nv_bfloat16 d_wlo[COUT * COUT];

// ---------------- helpers ----------------
__device__ __forceinline__ uint32_t smem_u32(const void* p){
    uint32_t a;
    asm("{ .reg .u64 t; cvta.to.shared.u64 t, %1; cvt.u32.u64 %0, t; }" : "=r"(a) : "l"(p));
    return a;
}
__device__ __forceinline__ void ldsm4(uint32_t* r, uint32_t addr){
    asm volatile("ldmatrix.sync.aligned.m8n8.x4.shared.b16 {%0,%1,%2,%3}, [%4];"
        : "=r"(r[0]), "=r"(r[1]), "=r"(r[2]), "=r"(r[3]) : "r"(addr));
}
__device__ __forceinline__ void mma16816(float* d, const uint32_t* a, uint32_t b0, uint32_t b1){
    asm volatile("mma.sync.aligned.m16n8k16.row.col.f32.bf16.bf16.f32 "
        "{%0,%1,%2,%3}, {%4,%5,%6,%7}, {%8,%9}, {%0,%1,%2,%3};"
        : "+f"(d[0]), "+f"(d[1]), "+f"(d[2]), "+f"(d[3])
        : "r"(a[0]), "r"(a[1]), "r"(a[2]), "r"(a[3]), "r"(b0), "r"(b1));
}
__device__ __forceinline__ void split2(float f, __nv_bfloat16& h, __nv_bfloat16& lo){
    h  = __float2bfloat16(f);
    lo = __float2bfloat16(f - __bfloat162float(h));
}
__device__ __forceinline__ uint32_t packp(float a, float b){
    __nv_bfloat162 h = __floats2bfloat162_rn(a, b);
    return *reinterpret_cast<uint32_t*>(&h);
}
__device__ __forceinline__ uint32_t pack2h(__nv_bfloat16 a, __nv_bfloat16 b){
    __nv_bfloat162 h; h.x = a; h.y = b;
    return *reinterpret_cast<uint32_t*>(&h);
}
__device__ __forceinline__ void cpa16(uint32_t s, const void* g){
    unsigned long long ga = __cvta_generic_to_global(g);
    asm volatile("cp.async.cg.shared.global [%0], [%1], 16;" :: "r"(s), "l"(ga));
}
__device__ __forceinline__ void cpa_commit(){ asm volatile("cp.async.commit_group;"); }
__device__ __forceinline__ void cpa_wait0(){ asm volatile("cp.async.wait_group 0;" ::: "memory"); }
__device__ __forceinline__ void cpa_wait1(){ asm volatile("cp.async.wait_group 1;" ::: "memory"); }

// ---------------- prep kernels ----------------
__global__ void prep_kT(const float* __restrict__ x,
                        __nv_bfloat16* __restrict__ kThi, __nv_bfloat16* __restrict__ kTlo)
{
    __shared__ float tile[32][33];
    const int n0 = blockIdx.x * 32, c0 = blockIdx.y * 32, b = blockIdx.z;
    const float* xb = x + (size_t)b * CIN * NTOK;
    const int lane = threadIdx.x & 31, grp = threadIdx.x >> 5;
    #pragma unroll
    for (int i = 0; i < 4; ++i){
        const int c = i * 8 + grp, n = n0 + lane;
        tile[c][lane] = (n < NTOK) ? xb[(size_t)(c0 + c) * NTOK + n] : 0.0f;
    }
    __syncthreads();
    #pragma unroll
    for (int i = 0; i < 4; ++i){
        const int tok = i * 8 + grp, c = lane;
        __nv_bfloat16 h, lo;
        split2(tile[c][tok], h, lo);
        const size_t o = ((size_t)b * NPAD + n0 + tok) * CIN + c0 + c;
        kThi[o] = h; kTlo[o] = lo;
    }
}

__global__ void prep_m(const float* __restrict__ x, float* __restrict__ m)
{
    const int n = blockIdx.x * 256 + threadIdx.x;
    const int b = blockIdx.y;
    if (n < NTOK){
        const float* xb = x + (size_t)b * CIN * NTOK + n;
        float s = 0.0f;
        #pragma unroll 8
        for (int c = 0; c < CIN; ++c){ float f = xb[(size_t)c * NTOK]; s = fmaf(f, f, s); }
        m[b * NTOK + n] = s;
    }
}

// merged: w split (blocks [0,144)) + xjT pad zero / stats zero (blocks [144,336))
__global__ void prep_misc(const float* __restrict__ w,
                          __nv_bfloat16* __restrict__ whi, __nv_bfloat16* __restrict__ wlo,
                          __nv_bfloat16* __restrict__ xjThi, __nv_bfloat16* __restrict__ xjTlo,
                          float* __restrict__ stats)
{
    const int tid = threadIdx.x;
    if (blockIdx.x < 144){
        const int i = blockIdx.x * 256 + tid;     // < 36864
        __nv_bfloat16 h, lo;
        split2(w[i], h, lo);
        whi[i] = h; wlo[i] = lo;
    } else {
        const int idx = (blockIdx.x - 144) * 256 + tid;  // < 49152
        const int b = idx / ((NPAD - NTOK) * CIN);
        const int r = idx % ((NPAD - NTOK) * CIN);
        const size_t o = ((size_t)b * NPAD + NTOK) * CIN + r;
        xjThi[o] = __float2bfloat16(0.0f);
        xjTlo[o] = __float2bfloat16(0.0f);
        if (idx < 2 * COUT) stats[idx] = 0.0f;
    }
}

// ---------------- attention ----------------
// smem: QHI 0 (26624, dead after preload -> KLO @0, Ost @0)
//       KHI0 26624, KHI1 39936 (13312 each)
//       QLO 53248 (26624, persistent)
//       VHI 79872, VLO 93696 (13824 each)
#define O_QHI  0
#define O_KLO  0
#define O_KHI0 26624
#define O_KHI1 39936
#define O_QLO  53248
#define O_VHI  79872
#define O_VLO  93696
#define ATT_SMEM 107520
#define NKT 49
#define NQB 25

__device__ __forceinline__ void issue_khi(uint32_t dst, const char* kThi, int t){
    const int n1 = t * 64;
    #pragma unroll
    for (int i = 0; i < 3; ++i){
        const int q = threadIdx.x + i * 256;
        const int row = q / 12, cb = q % 12;
        cpa16(dst + row * 208 + cb * 16, kThi + (size_t)(n1 + row) * 192 + cb * 16);
    }
}

__device__ __forceinline__ void gemm1_pass(float S[8][4], const uint32_t A[6][4], uint32_t kb){
    #pragma unroll
    for (int kk = 0; kk < 6; ++kk){
        #pragma unroll
        for (int g = 0; g < 4; ++g){
            uint32_t bb[4];
            ldsm4(bb, kb + (uint32_t)(g * 16 * 208 + kk * 32));
            mma16816(S[2 * g],     A[kk], bb[0], bb[2]);
            mma16816(S[2 * g + 1], A[kk], bb[1], bb[3]);
        }
    }
}
__device__ __forceinline__ void gemm2_pass(float O[12][4], const uint32_t A[4][4], uint32_t vb){
    #pragma unroll
    for (int kt = 0; kt < 4; ++kt){
        #pragma unroll
        for (int g = 0; g < 6; ++g){
            uint32_t bb[4];
            ldsm4(bb, vb + (uint32_t)(g * 16 * 144 + kt * 32));
            mma16816(O[2 * g],     A[kt], bb[0], bb[2]);
            mma16816(O[2 * g + 1], A[kt], bb[1], bb[3]);
        }
    }
}

__global__ __launch_bounds__(256, 2)
void attn_mma(const float* __restrict__ x_g,
              const __nv_bfloat16* __restrict__ kThi_g, const __nv_bfloat16* __restrict__ kTlo_g,
              const float* __restrict__ m_g,
              __nv_bfloat16* __restrict__ xjThi_g, __nv_bfloat16* __restrict__ xjTlo_g)
{
    extern __shared__ char sm[];
    const int tid = threadIdx.x, w = tid >> 5, ln = tid & 31;
    const int b = blockIdx.y, n0 = blockIdx.x * 128;
    const uint32_t smb = smem_u32(sm);
    const char* kThi = (const char*)(kThi_g + (size_t)b * NPAD * CIN);
    const char* kTlo = (const char*)(kTlo_g + (size_t)b * NPAD * CIN);
    const float* xb = x_g + (size_t)b * CIN * NTOK;

    // group0: Q hi+lo
    #pragma unroll
    for (int i = 0; i < 6; ++i){
        const int q = tid + i * 256;
        const int row = q / 12, cb = q % 12;
        cpa16(smb + O_QHI + row * 208 + cb * 16, kThi + (size_t)(n0 + row) * 192 + cb * 16);
        cpa16(smb + O_QLO + row * 208 + cb * 16, kTlo + (size_t)(n0 + row) * 192 + cb * 16);
    }
    cpa_commit();
    // group1: khi tile0
    issue_khi(smb + O_KHI0, kThi, 0);
    cpa_commit();

    const int r0 = 16 * w + (ln >> 2), r1 = r0 + 8;
    const float M0 = (n0 + r0 < NTOK) ? m_g[b * NTOK + n0 + r0] : 3.0e38f;
    const float M1 = (n0 + r1 < NTOK) ? m_g[b * NTOK + n0 + r1] : 3.0e38f;

    cpa_wait1();           // Q ready
    __syncthreads();

    const int arow = ((ln >> 3) & 1) * 8 + (ln & 7);
    const int acol = (ln >> 4) * 8;
    uint32_t Qh[6][4];
    {
        const uint32_t aq = smb + O_QHI + (uint32_t)((16 * w + arow) * 208 + acol * 2);
        #pragma unroll
        for (int kk = 0; kk < 6; ++kk) ldsm4(Qh[kk], aq + kk * 32);
    }
    __syncthreads();       // QHI region now reusable

    float O[12][4];
    #pragma unroll
    for (int n = 0; n < 12; ++n){ O[n][0]=0.f; O[n][1]=0.f; O[n][2]=0.f; O[n][3]=0.f; }
    float L0 = 0.0f, L1 = 0.0f;

    for (int t = 0; t < NKT; ++t){
        if (t + 1 < NKT){
            issue_khi(smb + ((t + 1) & 1 ? O_KHI1 : O_KHI0), kThi, t + 1);
            cpa_commit();
            cpa_wait1();
        } else {
            cpa_wait0();
        }
        __syncthreads();

        const uint32_t kb = smb + (t & 1 ? O_KHI1 : O_KHI0) + (uint32_t)(arow * 208 + acol * 2);
        float S[8][4];
        #pragma unroll
        for (int n = 0; n < 8; ++n){ S[n][0]=0.f; S[n][1]=0.f; S[n][2]=0.f; S[n][3]=0.f; }
        gemm1_pass(S, Qh, kb);

        float mx = -3.0e38f;
        #pragma unroll
        for (int n = 0; n < 8; ++n){
            mx = fmaxf(mx, fmaxf(S[n][0], S[n][1]) - M0);
            mx = fmaxf(mx, fmaxf(S[n][2], S[n][3]) - M1);
        }
        const int need = __syncthreads_or(mx >= -19.0f);
        // NOTE: this vote barrier also orders all cross-warp reuse of the
        // single-buffered KLO/VHI/VLO regions between consecutive needed
        // tiles, so no loop-end __syncthreads is required.

        if (need){
            const int n1 = t * 64;
            // lazy stage klo via cp.async
            #pragma unroll
            for (int i = 0; i < 3; ++i){
                const int q = tid + i * 256;
                const int row = q / 12, cb = q % 12;
                cpa16(smb + O_KLO + row * 208 + cb * 16, kTlo + (size_t)(n1 + row) * 192 + cb * 16);
            }
            cpa_commit();
            // on-demand V convert from fp32 x (overlaps the klo cp.async)
            {
                const float* xv = xb + n1;
                #pragma unroll 4
                for (int idx = tid; idx < 96 * 32; idx += 256){
                    const int c = idx >> 5, tp = idx & 31;     // channel, token-pair
                    const float2 f = *(const float2*)&xv[(size_t)c * NTOK + 2 * tp];
                    __nv_bfloat16 h0, l0, h1, l1;
                    split2(f.x, h0, l0); split2(f.y, h1, l1);
                    *(uint32_t*)(sm + O_VHI + c * 144 + 4 * tp) = pack2h(h0, h1);
                    *(uint32_t*)(sm + O_VLO + c * 144 + 4 * tp) = pack2h(l0, l1);
                }
            }
            cpa_wait0();
            __syncthreads();

            gemm1_pass(S, Qh, smb + O_KLO + (uint32_t)(arow * 208 + acol * 2));
            uint32_t Ql[6][4];
            {
                const uint32_t aq = smb + O_QLO + (uint32_t)((16 * w + arow) * 208 + acol * 2);
                #pragma unroll
                for (int kk = 0; kk < 6; ++kk) ldsm4(Ql[kk], aq + kk * 32);
            }
            gemm1_pass(S, Ql, kb);

            uint32_t Ph[4][4], Pl[4][4];
            #pragma unroll
            for (int n = 0; n < 8; ++n){
                const float p0 = __expf(S[n][0] - M0);
                const float p1 = __expf(S[n][1] - M0);
                const float p2 = __expf(S[n][2] - M1);
                const float p3 = __expf(S[n][3] - M1);
                L0 += p0 + p1;
                L1 += p2 + p3;
                const int kt = n >> 1, hh = (n & 1) * 2;
                Ph[kt][hh]     = packp(p0, p1);
                Ph[kt][hh + 1] = packp(p2, p3);
                const float q0 = p0 - __bfloat162float(__float2bfloat16(p0));
                const float q1 = p1 - __bfloat162float(__float2bfloat16(p1));
                const float q2 = p2 - __bfloat162float(__float2bfloat16(p2));
                const float q3 = p3 - __bfloat162float(__float2bfloat16(p3));
                Pl[kt][hh]     = packp(q0, q1);
                Pl[kt][hh + 1] = packp(q2, q3);
            }

            const uint32_t vb = smb + O_VHI + (uint32_t)(arow * 144 + acol * 2);
            gemm2_pass(O, Ph, vb);
            gemm2_pass(O, Ph, vb + (O_VLO - O_VHI));
            gemm2_pass(O, Pl, vb);
        }
    }
    __syncthreads();       // protect Ost overlay (KLO region) from last-tile reads

    L0 += __shfl_xor_sync(0xffffffffu, L0, 1);
    L0 += __shfl_xor_sync(0xffffffffu, L0, 2);
    L1 += __shfl_xor_sync(0xffffffffu, L1, 1);
    L1 += __shfl_xor_sync(0xffffffffu, L1, 2);
    const float inv0 = 1.0f / L0, inv1 = 1.0f / L1;

    // stage O/l in smem as [tok][c] f32, stride 100
    float* Ost = (float*)sm;
    #pragma unroll
    for (int n = 0; n < 12; ++n){
        const int c = 8 * n + 2 * (ln & 3);
        Ost[r0 * 100 + c]     = O[n][0] * inv0;
        Ost[r0 * 100 + c + 1] = O[n][1] * inv0;
        Ost[r1 * 100 + c]     = O[n][2] * inv1;
        Ost[r1 * 100 + c + 1] = O[n][3] * inv1;
    }
    __syncthreads();

    // xjT = relu(x~ - O/l), split to bf16 hi/lo, [tok][c]
    char* xjThi = (char*)(xjThi_g + (size_t)b * NPAD * CIN);
    char* xjTlo = (char*)(xjTlo_g + (size_t)b * NPAD * CIN);
    for (int idx = tid; idx < 128 * 48; idx += 256){
        const int row = idx / 48, cp = idx % 48;
        const int nq = n0 + row;
        if (nq < NTOK){
            const uint32_t hp = *(const uint32_t*)(kThi + (size_t)nq * 192 + cp * 4);
            const uint32_t lp = *(const uint32_t*)(kTlo + (size_t)nq * 192 + cp * 4);
            const __nv_bfloat162 hb = *reinterpret_cast<const __nv_bfloat162*>(&hp);
            const __nv_bfloat162 lb = *reinterpret_cast<const __nv_bfloat162*>(&lp);
            const float x0 = __bfloat162float(hb.x) + __bfloat162float(lb.x);
            const float x1 = __bfloat162float(hb.y) + __bfloat162float(lb.y);
            const float v0 = fmaxf(x0 - Ost[row * 100 + 2 * cp], 0.0f);
            const float v1 = fmaxf(x1 - Ost[row * 100 + 2 * cp + 1], 0.0f);
            __nv_bfloat16 h0, l0, h1, l1;
            split2(v0, h0, l0); split2(v1, h1, l1);
            *(uint32_t*)(xjThi + (size_t)nq * 192 + cp * 4) = pack2h(h0, h1);
            *(uint32_t*)(xjTlo + (size_t)nq * 192 + cp * 4) = pack2h(l0, l1);
        }
    }
}

// ---------------- conv via mma (3-pass bf16 split) ----------------
#define CV_SMEM 179200
__global__ __launch_bounds__(384, 1)
void conv_mma(const __nv_bfloat16* __restrict__ whi_g, const __nv_bfloat16* __restrict__ wlo_g,
              const __nv_bfloat16* __restrict__ kThi_g, const __nv_bfloat16* __restrict__ kTlo_g,
              const __nv_bfloat16* __restrict__ xjThi_g, const __nv_bfloat16* __restrict__ xjTlo_g,
              const float* __restrict__ bias, float* __restrict__ y, float* __restrict__ stats)
{
    extern __shared__ char sm[];
    const int tid = threadIdx.x, w = tid >> 5, ln = tid & 31;
    const int n0 = blockIdx.x * 128, o0 = blockIdx.y * 96, b = blockIdx.z;
    const uint32_t smb = smem_u32(sm);
    const char* whi = (const char*)whi_g;
    const char* wlo = (const char*)wlo_g;
    const char* kThi = (const char*)(kThi_g + (size_t)b * NPAD * CIN);
    const char* kTlo = (const char*)(kTlo_g + (size_t)b * NPAD * CIN);
    const char* xjThi = (const char*)(xjThi_g + (size_t)b * NPAD * CIN);
    const char* xjTlo = (const char*)(xjTlo_g + (size_t)b * NPAD * CIN);

    #pragma unroll
    for (int i = 0; i < 12; ++i){
        const int q = tid + i * 384;
        const int sel = q / 2304, r = q % 2304;
        const int row = r / 24, cb = r % 24;
        const char* src = (sel ? wlo : whi) + (size_t)(o0 + row) * 384 + cb * 16;
        cpa16(smb + sel * 38400 + row * 400 + cb * 16, src);
    }
    #pragma unroll
    for (int i = 0; i < 16; ++i){
        const int q = tid + i * 384;
        const int sel = q / 3072, r = q % 3072;
        const int row = r / 24, cb = r % 24;
        const char* src;
        if (cb < 12) src = (sel ? kTlo : kThi) + (size_t)(n0 + row) * 192 + cb * 16;
        else         src = (sel ? xjTlo : xjThi) + (size_t)(n0 + row) * 192 + (cb - 12) * 16;
        cpa16(smb + 76800 + sel * 51200 + row * 400 + cb * 16, src);
    }
    cpa_commit();
    cpa_wait0();
    __syncthreads();

    const int mb = w >> 1, nh = w & 1;
    const int arow = ((ln >> 3) & 1) * 8 + (ln & 7);
    const int acol = (ln >> 4) * 8;
    const uint32_t Wh = smb + (uint32_t)((mb * 16 + arow) * 400 + acol * 2);
    const uint32_t Wl = Wh + 38400;
    const uint32_t Xh = smb + 76800 + (uint32_t)((nh * 64 + arow) * 400 + acol * 2);
    const uint32_t Xl = Xh + 51200;

    float acc[8][4];
    #pragma unroll
    for (int k = 0; k < 8; ++k){ acc[k][0]=0.f; acc[k][1]=0.f; acc[k][2]=0.f; acc[k][3]=0.f; }

    #pragma unroll
    for (int ks = 0; ks < 12; ++ks){
        uint32_t Ah[4], Al[4];
        ldsm4(Ah, Wh + ks * 32);
        ldsm4(Al, Wl + ks * 32);
        #pragma unroll
        for (int g = 0; g < 4; ++g){
            uint32_t Bh[4], Bl[4];
            ldsm4(Bh, Xh + (uint32_t)(g * 16 * 400 + ks * 32));
            ldsm4(Bl, Xl + (uint32_t)(g * 16 * 400 + ks * 32));
            mma16816(acc[2 * g],     Ah, Bh[0], Bh[2]);
            mma16816(acc[2 * g + 1], Ah, Bh[1], Bh[3]);
            mma16816(acc[2 * g],     Ah, Bl[0], Bl[2]);
            mma16816(acc[2 * g + 1], Ah, Bl[1], Bl[3]);
            mma16816(acc[2 * g],     Al, Bh[0], Bh[2]);
            mma16816(acc[2 * g + 1], Al, Bh[1], Bh[3]);
        }
    }

    const int r0 = o0 + mb * 16 + (ln >> 2), r1 = r0 + 8;
    const float b0 = bias[r0], b1 = bias[r1];
    float* yb = y + (size_t)b * COUT * NTOK;
    float s10 = 0.f, s20 = 0.f, s11 = 0.f, s21 = 0.f;
    #pragma unroll
    for (int k = 0; k < 8; ++k){
        const int n = n0 + nh * 64 + (k >> 1) * 16 + (k & 1) * 8 + (ln & 3) * 2;
        if (n < NTOK){
            const float v0 = acc[k][0] + b0, v1 = acc[k][1] + b0;
            const float v2 = acc[k][2] + b1, v3 = acc[k][3] + b1;
            float2 p0; p0.x = v0; p0.y = v1;
            float2 p1; p1.x = v2; p1.y = v3;
            *(float2*)&yb[(size_t)r0 * NTOK + n] = p0;
            *(float2*)&yb[(size_t)r1 * NTOK + n] = p1;
            s10 += v0 + v1; s20 += v0 * v0 + v1 * v1;
            s11 += v2 + v3; s21 += v2 * v2 + v3 * v3;
        }
    }
    #pragma unroll
    for (int off = 1; off <= 2; off <<= 1){
        s10 += __shfl_xor_sync(0xffffffffu, s10, off);
        s20 += __shfl_xor_sync(0xffffffffu, s20, off);
        s11 += __shfl_xor_sync(0xffffffffu, s11, off);
        s21 += __shfl_xor_sync(0xffffffffu, s21, off);
    }
    if ((ln & 3) == 0){
        atomicAdd(&stats[r0], s10); atomicAdd(&stats[COUT + r0], s20);
        atomicAdd(&stats[r1], s11); atomicAdd(&stats[COUT + r1], s21);
    }
}

// ---------------- BN + GELU (per-channel-row blocks, no division) ----------------
#define NT4 (NTOK / 4)   // 784 float4 per channel row
__global__ void bn_gelu_row(const float4* __restrict__ y4, const float* __restrict__ stats,
                            const float* __restrict__ gamma, const float* __restrict__ beta,
                            float4* __restrict__ out4)
{
    const int o = blockIdx.y, b = blockIdx.z;
    const size_t base = ((size_t)b * COUT + o) * NT4;
    const float invN = 1.0f / (float)NPOS;
    const float mean = stats[o] * invN;
    const float var  = stats[COUT + o] * invN - mean * mean;
    const float sc   = rsqrtf(var + 1e-5f) * gamma[o];
    const float be   = beta[o] - mean * sc;
    for (int i = threadIdx.x; i < NT4; i += 256){
        float4 v = y4[base + i];
        float a0 = v.x * sc + be;
        float a1 = v.y * sc + be;
        float a2 = v.z * sc + be;
        float a3 = v.w * sc + be;
        v.x = 0.5f * a0 * (1.0f + erff(a0 * 0.70710678118654752f));
        v.y = 0.5f * a1 * (1.0f + erff(a1 * 0.70710678118654752f));
        v.z = 0.5f * a2 * (1.0f + erff(a2 * 0.70710678118654752f));
        v.w = 0.5f * a3 * (1.0f + erff(a3 * 0.70710678118654752f));
        out4[base + i] = v;
    }
}

// ---------------- launch ----------------
extern "C" void kernel_launch(void* const* d_in, const int* in_sizes, int n_in,
                              void* d_out, int out_size)
{
    const float* x      = (const float*)d_in[0];
    const float* conv_w = (const float*)d_in[1];
    const float* conv_b = (const float*)d_in[2];
    const float* gamma  = (const float*)d_in[3];
    const float* beta   = (const float*)d_in[4];
    float* out = (float*)d_out;

    float *y, *stats, *m;
    __nv_bfloat16 *kThi, *kTlo, *xjThi, *xjTlo, *whi, *wlo;
    cudaGetSymbolAddress((void**)&y, d_y);
    cudaGetSymbolAddress((void**)&stats, d_stats);
    cudaGetSymbolAddress((void**)&m, d_m);
    cudaGetSymbolAddress((void**)&kThi, d_kThi);
    cudaGetSymbolAddress((void**)&kTlo, d_kTlo);
    cudaGetSymbolAddress((void**)&xjThi, d_xjThi);
    cudaGetSymbolAddress((void**)&xjTlo, d_xjTlo);
    cudaGetSymbolAddress((void**)&whi, d_whi);
    cudaGetSymbolAddress((void**)&wlo, d_wlo);

    cudaFuncSetAttribute(attn_mma, cudaFuncAttributeMaxDynamicSharedMemorySize, ATT_SMEM);
    cudaFuncSetAttribute(conv_mma, cudaFuncAttributeMaxDynamicSharedMemorySize, CV_SMEM);

    dim3 tgrid(NPAD / 32, CIN / 32, BATCH);
    prep_kT<<<tgrid, 256>>>(x, kThi, kTlo);
    dim3 mgrid((NTOK + 255) / 256, BATCH);
    prep_m<<<mgrid, 256>>>(x, m);
    prep_misc<<<336, 256>>>(conv_w, whi, wlo, xjThi, xjTlo, stats);

    dim3 agrid(NQB, BATCH);
    attn_mma<<<agrid, 256, ATT_SMEM>>>(x, kThi, kTlo, m, xjThi, xjTlo);

    dim3 cgrid(NQB, 2, BATCH);
    conv_mma<<<cgrid, 384, CV_SMEM>>>(whi, wlo, kThi, kTlo, xjThi, xjTlo, conv_b, y, stats);

    dim3 bgrid(1, COUT, BATCH);
    bn_gelu_row<<<bgrid, 256>>>((const float4*)y, stats, gamma, beta, (float4*)out);
}

// round 16
// speedup vs baseline: 2.0764x; 2.0764x over previous
#include <cuda_runtime.h>
#include <cuda_bf16.h>
#include <cstdint>
#include <math.h>

#define BATCH 8
#define CIN   96
#define COUT  192
#define NTOK  3136
#define NPOS  (BATCH * NTOK)
#define NPAD  3200

__device__ float d_y[BATCH * COUT * NTOK];
__device__ float d_stats[2 * COUT];
__device__ float d_m[BATCH * NTOK];
__device__ __nv_bfloat16 d_kThi[BATCH * NPAD * CIN];   // x as [b][tok][c]
__device__ __nv_bfloat16 d_kTlo[BATCH * NPAD * CIN];
__device__ __nv_bfloat16 d_xjThi[BATCH * NPAD * CIN];  // xj as [b][tok][c]
__device__ __nv_bfloat16 d_xjTlo[BATCH * NPAD * CIN];
__device__ __nv_bfloat16 d_whi[COUT * COUT];
__device__ __nv_bfloat16 d_wlo[COUT * COUT];

// ---------------- helpers ----------------
__device__ __forceinline__ uint32_t smem_u32(const void* p){
    uint32_t a;
    asm("{ .reg .u64 t; cvta.to.shared.u64 t, %1; cvt.u32.u64 %0, t; }" : "=r"(a) : "l"(p));
    return a;
}
__device__ __forceinline__ void ldsm4(uint32_t* r, uint32_t addr){
    asm volatile("ldmatrix.sync.aligned.m8n8.x4.shared.b16 {%0,%1,%2,%3}, [%4];"
        : "=r"(r[0]), "=r"(r[1]), "=r"(r[2]), "=r"(r[3]) : "r"(addr));
}
__device__ __forceinline__ void mma16816(float* d, const uint32_t* a, uint32_t b0, uint32_t b1){
    asm volatile("mma.sync.aligned.m16n8k16.row.col.f32.bf16.bf16.f32 "
        "{%0,%1,%2,%3}, {%4,%5,%6,%7}, {%8,%9}, {%0,%1,%2,%3};"
        : "+f"(d[0]), "+f"(d[1]), "+f"(d[2]), "+f"(d[3])
        : "r"(a[0]), "r"(a[1]), "r"(a[2]), "r"(a[3]), "r"(b0), "r"(b1));
}
__device__ __forceinline__ void split2(float f, __nv_bfloat16& h, __nv_bfloat16& lo){
    h  = __float2bfloat16(f);
    lo = __float2bfloat16(f - __bfloat162float(h));
}
__device__ __forceinline__ uint32_t packp(float a, float b){
    __nv_bfloat162 h = __floats2bfloat162_rn(a, b);
    return *reinterpret_cast<uint32_t*>(&h);
}
__device__ __forceinline__ uint32_t pack2h(__nv_bfloat16 a, __nv_bfloat16 b){
    __nv_bfloat162 h; h.x = a; h.y = b;
    return *reinterpret_cast<uint32_t*>(&h);
}
__device__ __forceinline__ void cpa16(uint32_t s, const void* g){
    unsigned long long ga = __cvta_generic_to_global(g);
    asm volatile("cp.async.cg.shared.global [%0], [%1], 16;" :: "r"(s), "l"(ga));
}
__device__ __forceinline__ void cpa_commit(){ asm volatile("cp.async.commit_group;"); }
__device__ __forceinline__ void cpa_wait0(){ asm volatile("cp.async.wait_group 0;" ::: "memory"); }
__device__ __forceinline__ void cpa_wait1(){ asm volatile("cp.async.wait_group 1;" ::: "memory"); }

// ---------------- prep kernels ----------------
__global__ void prep_kT(const float* __restrict__ x,
                        __nv_bfloat16* __restrict__ kThi, __nv_bfloat16* __restrict__ kTlo)
{
    __shared__ float tile[32][33];
    const int n0 = blockIdx.x * 32, c0 = blockIdx.y * 32, b = blockIdx.z;
    const float* xb = x + (size_t)b * CIN * NTOK;
    const int lane = threadIdx.x & 31, grp = threadIdx.x >> 5;
    #pragma unroll
    for (int i = 0; i < 4; ++i){
        const int c = i * 8 + grp, n = n0 + lane;
        tile[c][lane] = (n < NTOK) ? xb[(size_t)(c0 + c) * NTOK + n] : 0.0f;
    }
    __syncthreads();
    #pragma unroll
    for (int i = 0; i < 4; ++i){
        const int tok = i * 8 + grp, c = lane;
        __nv_bfloat16 h, lo;
        split2(tile[c][tok], h, lo);
        const size_t o = ((size_t)b * NPAD + n0 + tok) * CIN + c0 + c;
        kThi[o] = h; kTlo[o] = lo;
    }
}

__global__ void prep_m(const float* __restrict__ x, float* __restrict__ m)
{
    const int n = blockIdx.x * 256 + threadIdx.x;
    const int b = blockIdx.y;
    if (n < NTOK){
        const float* xb = x + (size_t)b * CIN * NTOK + n;
        float s = 0.0f;
        #pragma unroll 8
        for (int c = 0; c < CIN; ++c){ float f = xb[(size_t)c * NTOK]; s = fmaf(f, f, s); }
        m[b * NTOK + n] = s;
    }
}

// merged: w split (blocks [0,144)) + xjT pad zero / stats zero (blocks [144,336))
__global__ void prep_misc(const float* __restrict__ w,
                          __nv_bfloat16* __restrict__ whi, __nv_bfloat16* __restrict__ wlo,
                          __nv_bfloat16* __restrict__ xjThi, __nv_bfloat16* __restrict__ xjTlo,
                          float* __restrict__ stats)
{
    const int tid = threadIdx.x;
    if (blockIdx.x < 144){
        const int i = blockIdx.x * 256 + tid;     // < 36864
        __nv_bfloat16 h, lo;
        split2(w[i], h, lo);
        whi[i] = h; wlo[i] = lo;
    } else {
        const int idx = (blockIdx.x - 144) * 256 + tid;  // < 49152
        const int b = idx / ((NPAD - NTOK) * CIN);
        const int r = idx % ((NPAD - NTOK) * CIN);
        const size_t o = ((size_t)b * NPAD + NTOK) * CIN + r;
        xjThi[o] = __float2bfloat16(0.0f);
        xjTlo[o] = __float2bfloat16(0.0f);
        if (idx < 2 * COUT) stats[idx] = 0.0f;
    }
}

// ---------------- attention (64-row Q tiles, 128 threads, occ 4) ----------------
// smem (bytes):
//   T_KHI0 0      (13312)  bf16 K-hi double buffer
//   T_KHI1 13312  (13312)
//   T_SCR  26624  (27648)  scratch, time-multiplexed:
//       prologue: QHI [64][208]                (13312)
//       needed phase1: KLO @+0, QLO @+13312    (26624)
//       needed phase2: VHI @+0, VLO @+13824    (27648)
//   epilogue Ost: f32 [64][100] at offset 0 (KHI region, 25600)
#define T_KHI0 0
#define T_KHI1 13312
#define T_SCR  26624
#define ATT_SMEM 54272
#define NKT 49
#define NQB 49

__device__ __forceinline__ void issue_khi(uint32_t dst, const char* kThi, int t){
    const int n1 = t * 64;
    #pragma unroll
    for (int i = 0; i < 6; ++i){
        const int q = threadIdx.x + i * 128;       // 768 chunks (64 rows x 12)
        const int row = q / 12, cb = q % 12;
        cpa16(dst + row * 208 + cb * 16, kThi + (size_t)(n1 + row) * 192 + cb * 16);
    }
}

__device__ __forceinline__ void gemm1_pass(float S[8][4], const uint32_t A[6][4], uint32_t kb){
    #pragma unroll
    for (int kk = 0; kk < 6; ++kk){
        #pragma unroll
        for (int g = 0; g < 4; ++g){
            uint32_t bb[4];
            ldsm4(bb, kb + (uint32_t)(g * 16 * 208 + kk * 32));
            mma16816(S[2 * g],     A[kk], bb[0], bb[2]);
            mma16816(S[2 * g + 1], A[kk], bb[1], bb[3]);
        }
    }
}
__device__ __forceinline__ void gemm2_pass(float O[12][4], const uint32_t A[4][4], uint32_t vb){
    #pragma unroll
    for (int kt = 0; kt < 4; ++kt){
        #pragma unroll
        for (int g = 0; g < 6; ++g){
            uint32_t bb[4];
            ldsm4(bb, vb + (uint32_t)(g * 16 * 144 + kt * 32));
            mma16816(O[2 * g],     A[kt], bb[0], bb[2]);
            mma16816(O[2 * g + 1], A[kt], bb[1], bb[3]);
        }
    }
}

__global__ __launch_bounds__(128, 4)
void attn_mma(const float* __restrict__ x_g,
              const __nv_bfloat16* __restrict__ kThi_g, const __nv_bfloat16* __restrict__ kTlo_g,
              const float* __restrict__ m_g,
              __nv_bfloat16* __restrict__ xjThi_g, __nv_bfloat16* __restrict__ xjTlo_g)
{
    extern __shared__ char sm[];
    const int tid = threadIdx.x, w = tid >> 5, ln = tid & 31;
    const int b = blockIdx.y, n0 = blockIdx.x * 64;
    const uint32_t smb = smem_u32(sm);
    const char* kThi = (const char*)(kThi_g + (size_t)b * NPAD * CIN);
    const char* kTlo = (const char*)(kTlo_g + (size_t)b * NPAD * CIN);
    const float* xb = x_g + (size_t)b * CIN * NTOK;

    // group0: Q-hi into scratch
    #pragma unroll
    for (int i = 0; i < 6; ++i){
        const int q = tid + i * 128;
        const int row = q / 12, cb = q % 12;
        cpa16(smb + T_SCR + row * 208 + cb * 16, kThi + (size_t)(n0 + row) * 192 + cb * 16);
    }
    cpa_commit();
    // group1: khi tile0
    issue_khi(smb + T_KHI0, kThi, 0);
    cpa_commit();

    const int r0 = 16 * w + (ln >> 2), r1 = r0 + 8;   // rows 0..63, all valid (3136 = 49*64)
    const float M0 = m_g[b * NTOK + n0 + r0];
    const float M1 = m_g[b * NTOK + n0 + r1];

    cpa_wait1();           // Q-hi ready
    __syncthreads();

    const int arow = ((ln >> 3) & 1) * 8 + (ln & 7);
    const int acol = (ln >> 4) * 8;
    uint32_t Qh[6][4];
    {
        const uint32_t aq = smb + T_SCR + (uint32_t)((16 * w + arow) * 208 + acol * 2);
        #pragma unroll
        for (int kk = 0; kk < 6; ++kk) ldsm4(Qh[kk], aq + kk * 32);
    }
    __syncthreads();       // scratch reusable

    float O[12][4];
    #pragma unroll
    for (int n = 0; n < 12; ++n){ O[n][0]=0.f; O[n][1]=0.f; O[n][2]=0.f; O[n][3]=0.f; }
    float L0 = 0.0f, L1 = 0.0f;

    for (int t = 0; t < NKT; ++t){
        if (t + 1 < NKT){
            issue_khi(smb + ((t + 1) & 1 ? T_KHI1 : T_KHI0), kThi, t + 1);
            cpa_commit();
            cpa_wait1();
        } else {
            cpa_wait0();
        }
        __syncthreads();

        const uint32_t kb = smb + (t & 1 ? T_KHI1 : T_KHI0) + (uint32_t)(arow * 208 + acol * 2);
        float S[8][4];
        #pragma unroll
        for (int n = 0; n < 8; ++n){ S[n][0]=0.f; S[n][1]=0.f; S[n][2]=0.f; S[n][3]=0.f; }
        gemm1_pass(S, Qh, kb);

        float mx = -3.0e38f;
        #pragma unroll
        for (int n = 0; n < 8; ++n){
            mx = fmaxf(mx, fmaxf(S[n][0], S[n][1]) - M0);
            mx = fmaxf(mx, fmaxf(S[n][2], S[n][3]) - M1);
        }
        const int need = __syncthreads_or(mx >= -19.0f);
        // vote barrier orders all cross-warp reuse of scratch between tiles

        if (need){
            const int n1 = t * 64;
            // phase1 staging: KLO @scratch+0, QLO @scratch+13312
            #pragma unroll
            for (int i = 0; i < 6; ++i){
                const int q = tid + i * 128;
                const int row = q / 12, cb = q % 12;
                cpa16(smb + T_SCR + row * 208 + cb * 16,          kTlo + (size_t)(n1 + row) * 192 + cb * 16);
                cpa16(smb + T_SCR + 13312 + row * 208 + cb * 16,  kTlo + (size_t)(n0 + row) * 192 + cb * 16);
            }
            cpa_commit();
            cpa_wait0();
            __syncthreads();

            gemm1_pass(S, Qh, smb + T_SCR + (uint32_t)(arow * 208 + acol * 2));      // Qhi*Klo
            uint32_t Ql[6][4];
            {
                const uint32_t aq = smb + T_SCR + 13312 + (uint32_t)((16 * w + arow) * 208 + acol * 2);
                #pragma unroll
                for (int kk = 0; kk < 6; ++kk) ldsm4(Ql[kk], aq + kk * 32);
            }
            gemm1_pass(S, Ql, kb);                                                    // Qlo*Khi

            // softmax (regs only) before the scratch-overwrite barrier
            uint32_t Ph[4][4], Pl[4][4];
            #pragma unroll
            for (int n = 0; n < 8; ++n){
                const float p0 = __expf(S[n][0] - M0);
                const float p1 = __expf(S[n][1] - M0);
                const float p2 = __expf(S[n][2] - M1);
                const float p3 = __expf(S[n][3] - M1);
                L0 += p0 + p1;
                L1 += p2 + p3;
                const int kt = n >> 1, hh = (n & 1) * 2;
                Ph[kt][hh]     = packp(p0, p1);
                Ph[kt][hh + 1] = packp(p2, p3);
                const float q0 = p0 - __bfloat162float(__float2bfloat16(p0));
                const float q1 = p1 - __bfloat162float(__float2bfloat16(p1));
                const float q2 = p2 - __bfloat162float(__float2bfloat16(p2));
                const float q3 = p3 - __bfloat162float(__float2bfloat16(p3));
                Pl[kt][hh]     = packp(q0, q1);
                Pl[kt][hh + 1] = packp(q2, q3);
            }
            __syncthreads();   // all gemm1 scratch reads done

            // phase2: V convert into scratch (VHI @+0, VLO @+13824)
            {
                const float* xv = xb + n1;
                #pragma unroll 4
                for (int idx = tid; idx < 96 * 32; idx += 128){
                    const int c = idx >> 5, tp = idx & 31;
                    const float2 f = *(const float2*)&xv[(size_t)c * NTOK + 2 * tp];
                    __nv_bfloat16 h0, l0, h1, l1;
                    split2(f.x, h0, l0); split2(f.y, h1, l1);
                    *(uint32_t*)(sm + T_SCR + c * 144 + 4 * tp) = pack2h(h0, h1);
                    *(uint32_t*)(sm + T_SCR + 13824 + c * 144 + 4 * tp) = pack2h(l0, l1);
                }
            }
            __syncthreads();

            const uint32_t vb = smb + T_SCR + (uint32_t)(arow * 144 + acol * 2);
            gemm2_pass(O, Ph, vb);
            gemm2_pass(O, Ph, vb + 13824u);
            gemm2_pass(O, Pl, vb);
        }
    }
    __syncthreads();       // protect Ost overlay (KHI region) from last-tile reads

    L0 += __shfl_xor_sync(0xffffffffu, L0, 1);
    L0 += __shfl_xor_sync(0xffffffffu, L0, 2);
    L1 += __shfl_xor_sync(0xffffffffu, L1, 1);
    L1 += __shfl_xor_sync(0xffffffffu, L1, 2);
    const float inv0 = 1.0f / L0, inv1 = 1.0f / L1;

    // stage O/l in smem as [tok][c] f32, stride 100 (KHI region, 25600 B)
    float* Ost = (float*)sm;
    #pragma unroll
    for (int n = 0; n < 12; ++n){
        const int c = 8 * n + 2 * (ln & 3);
        Ost[r0 * 100 + c]     = O[n][0] * inv0;
        Ost[r0 * 100 + c + 1] = O[n][1] * inv0;
        Ost[r1 * 100 + c]     = O[n][2] * inv1;
        Ost[r1 * 100 + c + 1] = O[n][3] * inv1;
    }
    __syncthreads();

    // xjT = relu(x~ - O/l), split to bf16 hi/lo, [tok][c]
    char* xjThi = (char*)(xjThi_g + (size_t)b * NPAD * CIN);
    char* xjTlo = (char*)(xjTlo_g + (size_t)b * NPAD * CIN);
    for (int idx = tid; idx < 64 * 48; idx += 128){
        const int row = idx / 48, cp = idx % 48;
        const int nq = n0 + row;
        const uint32_t hp = *(const uint32_t*)(kThi + (size_t)nq * 192 + cp * 4);
        const uint32_t lp = *(const uint32_t*)(kTlo + (size_t)nq * 192 + cp * 4);
        const __nv_bfloat162 hb = *reinterpret_cast<const __nv_bfloat162*>(&hp);
        const __nv_bfloat162 lb = *reinterpret_cast<const __nv_bfloat162*>(&lp);
        const float x0 = __bfloat162float(hb.x) + __bfloat162float(lb.x);
        const float x1 = __bfloat162float(hb.y) + __bfloat162float(lb.y);
        const float v0 = fmaxf(x0 - Ost[row * 100 + 2 * cp], 0.0f);
        const float v1 = fmaxf(x1 - Ost[row * 100 + 2 * cp + 1], 0.0f);
        __nv_bfloat16 h0, l0, h1, l1;
        split2(v0, h0, l0); split2(v1, h1, l1);
        *(uint32_t*)(xjThi + (size_t)nq * 192 + cp * 4) = pack2h(h0, h1);
        *(uint32_t*)(xjTlo + (size_t)nq * 192 + cp * 4) = pack2h(l0, l1);
    }
}

// ---------------- conv via mma (3-pass bf16 split) ----------------
#define CV_SMEM 179200
__global__ __launch_bounds__(384, 1)
void conv_mma(const __nv_bfloat16* __restrict__ whi_g, const __nv_bfloat16* __restrict__ wlo_g,
              const __nv_bfloat16* __restrict__ kThi_g, const __nv_bfloat16* __restrict__ kTlo_g,
              const __nv_bfloat16* __restrict__ xjThi_g, const __nv_bfloat16* __restrict__ xjTlo_g,
              const float* __restrict__ bias, float* __restrict__ y, float* __restrict__ stats)
{
    extern __shared__ char sm[];
    const int tid = threadIdx.x, w = tid >> 5, ln = tid & 31;
    const int n0 = blockIdx.x * 128, o0 = blockIdx.y * 96, b = blockIdx.z;
    const uint32_t smb = smem_u32(sm);
    const char* whi = (const char*)whi_g;
    const char* wlo = (const char*)wlo_g;
    const char* kThi = (const char*)(kThi_g + (size_t)b * NPAD * CIN);
    const char* kTlo = (const char*)(kTlo_g + (size_t)b * NPAD * CIN);
    const char* xjThi = (const char*)(xjThi_g + (size_t)b * NPAD * CIN);
    const char* xjTlo = (const char*)(xjTlo_g + (size_t)b * NPAD * CIN);

    #pragma unroll
    for (int i = 0; i < 12; ++i){
        const int q = tid + i * 384;
        const int sel = q / 2304, r = q % 2304;
        const int row = r / 24, cb = r % 24;
        const char* src = (sel ? wlo : whi) + (size_t)(o0 + row) * 384 + cb * 16;
        cpa16(smb + sel * 38400 + row * 400 + cb * 16, src);
    }
    #pragma unroll
    for (int i = 0; i < 16; ++i){
        const int q = tid + i * 384;
        const int sel = q / 3072, r = q % 3072;
        const int row = r / 24, cb = r % 24;
        const char* src;
        if (cb < 12) src = (sel ? kTlo : kThi) + (size_t)(n0 + row) * 192 + cb * 16;
        else         src = (sel ? xjTlo : xjThi) + (size_t)(n0 + row) * 192 + (cb - 12) * 16;
        cpa16(smb + 76800 + sel * 51200 + row * 400 + cb * 16, src);
    }
    cpa_commit();
    cpa_wait0();
    __syncthreads();

    const int mb = w >> 1, nh = w & 1;
    const int arow = ((ln >> 3) & 1) * 8 + (ln & 7);
    const int acol = (ln >> 4) * 8;
    const uint32_t Wh = smb + (uint32_t)((mb * 16 + arow) * 400 + acol * 2);
    const uint32_t Wl = Wh + 38400;
    const uint32_t Xh = smb + 76800 + (uint32_t)((nh * 64 + arow) * 400 + acol * 2);
    const uint32_t Xl = Xh + 51200;

    float acc[8][4];
    #pragma unroll
    for (int k = 0; k < 8; ++k){ acc[k][0]=0.f; acc[k][1]=0.f; acc[k][2]=0.f; acc[k][3]=0.f; }

    #pragma unroll
    for (int ks = 0; ks < 12; ++ks){
        uint32_t Ah[4], Al[4];
        ldsm4(Ah, Wh + ks * 32);
        ldsm4(Al, Wl + ks * 32);
        #pragma unroll
        for (int g = 0; g < 4; ++g){
            uint32_t Bh[4], Bl[4];
            ldsm4(Bh, Xh + (uint32_t)(g * 16 * 400 + ks * 32));
            ldsm4(Bl, Xl + (uint32_t)(g * 16 * 400 + ks * 32));
            mma16816(acc[2 * g],     Ah, Bh[0], Bh[2]);
            mma16816(acc[2 * g + 1], Ah, Bh[1], Bh[3]);
            mma16816(acc[2 * g],     Ah, Bl[0], Bl[2]);
            mma16816(acc[2 * g + 1], Ah, Bl[1], Bl[3]);
            mma16816(acc[2 * g],     Al, Bh[0], Bh[2]);
            mma16816(acc[2 * g + 1], Al, Bh[1], Bh[3]);
        }
    }

    const int r0 = o0 + mb * 16 + (ln >> 2), r1 = r0 + 8;
    const float b0 = bias[r0], b1 = bias[r1];
    float* yb = y + (size_t)b * COUT * NTOK;
    float s10 = 0.f, s20 = 0.f, s11 = 0.f, s21 = 0.f;
    #pragma unroll
    for (int k = 0; k < 8; ++k){
        const int n = n0 + nh * 64 + (k >> 1) * 16 + (k & 1) * 8 + (ln & 3) * 2;
        if (n < NTOK){
            const float v0 = acc[k][0] + b0, v1 = acc[k][1] + b0;
            const float v2 = acc[k][2] + b1, v3 = acc[k][3] + b1;
            float2 p0; p0.x = v0; p0.y = v1;
            float2 p1; p1.x = v2; p1.y = v3;
            *(float2*)&yb[(size_t)r0 * NTOK + n] = p0;
            *(float2*)&yb[(size_t)r1 * NTOK + n] = p1;
            s10 += v0 + v1; s20 += v0 * v0 + v1 * v1;
            s11 += v2 + v3; s21 += v2 * v2 + v3 * v3;
        }
    }
    #pragma unroll
    for (int off = 1; off <= 2; off <<= 1){
        s10 += __shfl_xor_sync(0xffffffffu, s10, off);
        s20 += __shfl_xor_sync(0xffffffffu, s20, off);
        s11 += __shfl_xor_sync(0xffffffffu, s11, off);
        s21 += __shfl_xor_sync(0xffffffffu, s21, off);
    }
    if ((ln & 3) == 0){
        atomicAdd(&stats[r0], s10); atomicAdd(&stats[COUT + r0], s20);
        atomicAdd(&stats[r1], s11); atomicAdd(&stats[COUT + r1], s21);
    }
}

// ---------------- BN + GELU (per-channel-row blocks) ----------------
#define NT4 (NTOK / 4)
__global__ void bn_gelu_row(const float4* __restrict__ y4, const float* __restrict__ stats,
                            const float* __restrict__ gamma, const float* __restrict__ beta,
                            float4* __restrict__ out4)
{
    const int o = blockIdx.y, b = blockIdx.z;
    const size_t base = ((size_t)b * COUT + o) * NT4;
    const float invN = 1.0f / (float)NPOS;
    const float mean = stats[o] * invN;
    const float var  = stats[COUT + o] * invN - mean * mean;
    const float sc   = rsqrtf(var + 1e-5f) * gamma[o];
    const float be   = beta[o] - mean * sc;
    for (int i = threadIdx.x; i < NT4; i += 256){
        float4 v = y4[base + i];
        float a0 = v.x * sc + be;
        float a1 = v.y * sc + be;
        float a2 = v.z * sc + be;
        float a3 = v.w * sc + be;
        v.x = 0.5f * a0 * (1.0f + erff(a0 * 0.70710678118654752f));
        v.y = 0.5f * a1 * (1.0f + erff(a1 * 0.70710678118654752f));
        v.z = 0.5f * a2 * (1.0f + erff(a2 * 0.70710678118654752f));
        v.w = 0.5f * a3 * (1.0f + erff(a3 * 0.70710678118654752f));
        out4[base + i] = v;
    }
}

// ---------------- launch ----------------
extern "C" void kernel_launch(void* const* d_in, const int* in_sizes, int n_in,
                              void* d_out, int out_size)
{
    const float* x      = (const float*)d_in[0];
    const float* conv_w = (const float*)d_in[1];
    const float* conv_b = (const float*)d_in[2];
    const float* gamma  = (const float*)d_in[3];
    const float* beta   = (const float*)d_in[4];
    float* out = (float*)d_out;

    float *y, *stats, *m;
    __nv_bfloat16 *kThi, *kTlo, *xjThi, *xjTlo, *whi, *wlo;
    cudaGetSymbolAddress((void**)&y, d_y);
    cudaGetSymbolAddress((void**)&stats, d_stats);
    cudaGetSymbolAddress((void**)&m, d_m);
    cudaGetSymbolAddress((void**)&kThi, d_kThi);
    cudaGetSymbolAddress((void**)&kTlo, d_kTlo);
    cudaGetSymbolAddress((void**)&xjThi, d_xjThi);
    cudaGetSymbolAddress((void**)&xjTlo, d_xjTlo);
    cudaGetSymbolAddress((void**)&whi, d_whi);
    cudaGetSymbolAddress((void**)&wlo, d_wlo);

    cudaFuncSetAttribute(attn_mma, cudaFuncAttributeMaxDynamicSharedMemorySize, ATT_SMEM);
    cudaFuncSetAttribute(conv_mma, cudaFuncAttributeMaxDynamicSharedMemorySize, CV_SMEM);

    dim3 tgrid(NPAD / 32, CIN / 32, BATCH);
    prep_kT<<<tgrid, 256>>>(x, kThi, kTlo);
    dim3 mgrid((NTOK + 255) / 256, BATCH);
    prep_m<<<mgrid, 256>>>(x, m);
    prep_misc<<<336, 256>>>(conv_w, whi, wlo, xjThi, xjTlo, stats);

    dim3 agrid(NQB, BATCH);
    attn_mma<<<agrid, 128, ATT_SMEM>>>(x, kThi, kTlo, m, xjThi, xjTlo);

    dim3 cgrid(25, 2, BATCH);
    conv_mma<<<cgrid, 384, CV_SMEM>>>(whi, wlo, kThi, kTlo, xjThi, xjTlo, conv_b, y, stats);

    dim3 bgrid(1, COUT, BATCH);
    bn_gelu_row<<<bgrid, 256>>>((const float4*)y, stats, gamma, beta, (float4*)out);
}